// round 15
// baseline (speedup 1.0000x reference)
#include <cuda_runtime.h>
#include <cuda_fp16.h>
#include <math.h>
#include <stdint.h>

#define NN 100000
#define LEAKY 0.2f

constexpr int LDH  = 66;   // u32 row stride for K=128 fp16 tiles (64 + 2 pad)
constexpr int LDHB = 34;   // u32 row stride for K=64  fp16 tiles (32 + 2 pad)

// ---------------- scratch (device globals; no allocation allowed) -----------
__device__ __half g_nt  [(size_t)NN * 128];
__device__ __half g_P   [(size_t)NN * 128];
__device__ __half g_h1h [(size_t)NN * 128];
__device__ __half g_gi  [(size_t)NN * 384];
__device__ __half g_gh  [(size_t)NN * 384];
__device__ float  g_h1  [(size_t)NN * 128];
__device__ float  g_scr [(size_t)NN * 8];
// fp16 weight copies
__device__ __half g_W1h [128 * 128];
__device__ __half g_Wah [128 * 128];
__device__ __half g_W2h [128 * 192];
__device__ __half g_Wihh[384 * 128];
__device__ __half g_Whhh[384 * 128];

__device__ __forceinline__ float lrelu_f(float x) { return x > 0.f ? x : LEAKY * x; }

__device__ __forceinline__ uint32_t h2u(__half2 h) {
    return *reinterpret_cast<uint32_t*>(&h);
}
__device__ __forceinline__ float2 u2f2(uint32_t u) {
    return __half22float2(*reinterpret_cast<__half2*>(&u));
}

__device__ __forceinline__ void mma_f16(float c[4], uint32_t a0, uint32_t a1,
                                        uint32_t a2, uint32_t a3,
                                        uint32_t b0, uint32_t b1) {
    asm volatile(
        "mma.sync.aligned.m16n8k16.row.col.f32.f16.f16.f32 "
        "{%0,%1,%2,%3}, {%4,%5,%6,%7}, {%8,%9}, {%0,%1,%2,%3};"
        : "+f"(c[0]), "+f"(c[1]), "+f"(c[2]), "+f"(c[3])
        : "r"(a0), "r"(a1), "r"(a2), "r"(a3), "r"(b0), "r"(b1));
}

// ---------------------------------------------------------------------------
__global__ void wconvert(const float* __restrict__ W1, const float* __restrict__ Wa,
                         const float* __restrict__ W2, const float* __restrict__ Wih,
                         const float* __restrict__ Whh) {
    int i = blockIdx.x * 256 + threadIdx.x;
    if (i < 16384) { g_W1h[i] = __float2half(W1[i]); g_Wah[i] = __float2half(Wa[i]); }
    if (i < 24576) g_W2h[i] = __float2half(W2[i]);
    if (i < 49152) { g_Wihh[i] = __float2half(Wih[i]); g_Whhh[i] = __float2half(Whh[i]); }
}

// ---------------------------------------------------------------------------
// Stage f32 [rows x (qk*4)] block as fp16 into smem u32 [.][ldh].
// ---------------------------------------------------------------------------
__device__ __forceinline__ void stage_h(uint32_t* __restrict__ dst,
                                        const float* __restrict__ srcp,
                                        int srcK, int koff,
                                        int rows_valid, int rows_total,
                                        int qk, int ldh) {
    const int tid = threadIdx.x;
    for (int idx = tid; idx < rows_total * qk; idx += blockDim.x) {
        int row = idx / qk;
        int q   = idx - row * qk;
        float4 v = make_float4(0.f, 0.f, 0.f, 0.f);
        if (row < rows_valid) v = *(const float4*)(srcp + (size_t)row * srcK + koff + q * 4);
        uint32_t* d = dst + row * ldh + q * 2;
        d[0] = h2u(__floats2half2_rn(v.x, v.y));
        d[1] = h2u(__floats2half2_rn(v.z, v.w));
    }
}

// Stage fp16 source directly: QK4 uint4 (=8 halves) per row.
template <int QK4>
__device__ __forceinline__ void stage_h16(uint32_t* __restrict__ dst,
                                          const __half* __restrict__ srcp,
                                          int srcK, int rows_valid,
                                          int rows_total, int ldh) {
    const int tid = threadIdx.x;
    for (int idx = tid; idx < rows_total * QK4; idx += blockDim.x) {
        int row = idx / QK4;
        int q   = idx - row * QK4;
        uint4 v = make_uint4(0u, 0u, 0u, 0u);
        if (row < rows_valid) v = *(const uint4*)(srcp + (size_t)row * srcK + q * 8);
        uint32_t* d = dst + row * ldh + q * 4;
        d[0] = v.x; d[1] = v.y; d[2] = v.z; d[3] = v.w;
    }
}

// ---------------------------------------------------------------------------
// Warp-tile fp16 mainloop. NKS k16 steps, 4 m16 x 4 n8 tiles per warp.
// ---------------------------------------------------------------------------
template <int NKS, int LDH_>
__device__ __forceinline__ void mma_loop_h(const uint32_t* __restrict__ As,
                                           const uint32_t* __restrict__ Ws,
                                           int wm, int wn, int g, int tg,
                                           float c[4][4][4]) {
#pragma unroll
    for (int ks = 0; ks < NKS; ks++) {
        uint32_t b[4][2];
#pragma unroll
        for (int nt = 0; nt < 4; nt++) {
            const uint32_t* bp = Ws + (wn * 32 + nt * 8 + g) * LDH_ + ks * 8 + tg;
            b[nt][0] = bp[0];
            b[nt][1] = bp[4];
        }
#pragma unroll
        for (int mt = 0; mt < 4; mt++) {
            const uint32_t* ap = As + (wm * 64 + mt * 16 + g) * LDH_ + ks * 8 + tg;
            uint32_t a0 = ap[0];
            uint32_t a1 = ap[8 * LDH_];
            uint32_t a2 = ap[4];
            uint32_t a3 = ap[8 * LDH_ + 4];
#pragma unroll
            for (int nt = 0; nt < 4; nt++)
                mma_f16(c[mt][nt], a0, a1, a2, a3, b[nt][0], b[nt][1]);
        }
    }
}

// ---------------------------------------------------------------------------
// Node GEMM (single n-tile): C[M x Nout] = act(A[M x 128] @ Wh^T + bias)
// AH: A fp16. CH: C fp16. DUP: also write fp16 copy to C2.
// ---------------------------------------------------------------------------
template <int ACT, bool AH, bool CH, bool DUP>
__global__ __launch_bounds__(256, 2)
void tc_gemm(const void* __restrict__ A_, const __half* __restrict__ Wh,
             const float* __restrict__ bias, void* __restrict__ C_,
             __half* __restrict__ C2, int M, int Nout, int wK) {
    extern __shared__ uint32_t smu[];
    uint32_t* As = smu;                 // [128][LDH]
    uint32_t* Ws = smu + 128 * LDH;     // [128][LDH]

    const int tid = threadIdx.x;
    const int m0 = blockIdx.y * 128;
    const int n0 = blockIdx.x * 128;
    const int wid = tid >> 5, lane = tid & 31;
    const int wm = wid >> 2, wn = wid & 3;
    const int g = lane >> 2, tg = lane & 3;

    if (AH) stage_h16<16>(As, (const __half*)A_ + (size_t)m0 * 128, 128, M - m0, 128, LDH);
    else    stage_h(As, (const float*)A_ + (size_t)m0 * 128, 128, 0, M - m0, 128, 32, LDH);
    stage_h16<16>(Ws, Wh + (size_t)n0 * wK, wK, 128, 128, LDH);
    __syncthreads();

    float c[4][4][4];
#pragma unroll
    for (int mt = 0; mt < 4; mt++)
#pragma unroll
        for (int nt = 0; nt < 4; nt++)
#pragma unroll
            for (int r = 0; r < 4; r++) c[mt][nt][r] = 0.f;

    mma_loop_h<8, LDH>(As, Ws, wm, wn, g, tg, c);

#pragma unroll
    for (int mt = 0; mt < 4; mt++) {
        int r0 = m0 + wm * 64 + mt * 16 + g;
#pragma unroll
        for (int nt = 0; nt < 4; nt++) {
            int col = n0 + wn * 32 + nt * 8 + tg * 2;
            float b0 = __ldg(bias + col), b1 = __ldg(bias + col + 1);
            float v0 = c[mt][nt][0] + b0, v1 = c[mt][nt][1] + b1;
            float v2 = c[mt][nt][2] + b0, v3 = c[mt][nt][3] + b1;
            if (ACT == 1) { v0 = lrelu_f(v0); v1 = lrelu_f(v1); v2 = lrelu_f(v2); v3 = lrelu_f(v3); }
            if (CH) {
                __half* C = (__half*)C_;
                if (r0 < M)     *(__half2*)(C + (size_t)r0 * Nout + col)       = __floats2half2_rn(v0, v1);
                if (r0 + 8 < M) *(__half2*)(C + (size_t)(r0 + 8) * Nout + col) = __floats2half2_rn(v2, v3);
            } else {
                float* C = (float*)C_;
                if (r0 < M)     *(float2*)(C + (size_t)r0 * Nout + col)       = make_float2(v0, v1);
                if (r0 + 8 < M) *(float2*)(C + (size_t)(r0 + 8) * Nout + col) = make_float2(v2, v3);
            }
            if (DUP) {
                if (r0 < M)     *(__half2*)(C2 + (size_t)r0 * Nout + col)       = __floats2half2_rn(v0, v1);
                if (r0 + 8 < M) *(__half2*)(C2 + (size_t)(r0 + 8) * Nout + col) = __floats2half2_rn(v2, v3);
            }
        }
    }
}

// ---------------------------------------------------------------------------
// gi kernel with fused ctx gather:
//   A-row n = elu( sum_e scr[n,e] * nt[src[n,e]] )  (built in smem, fp16)
//   gi[:, t*128 .. ] = A @ W_ih(t)^T + b_ih   for t = 0..2  (A resident)
// ---------------------------------------------------------------------------
__global__ __launch_bounds__(256, 2)
void gi_kernel(const int* __restrict__ src, const float* __restrict__ scr,
               const __half* __restrict__ nt, const __half* __restrict__ Wihh,
               const float* __restrict__ b_ih, __half* __restrict__ gi, int M) {
    extern __shared__ uint32_t smu[];
    uint32_t* As  = smu;                         // [128][LDH]
    uint32_t* Ws  = smu + 128 * LDH;             // [128][LDH]
    float* sscr   = (float*)(smu + 2 * 128 * LDH);  // [1024]
    int*   ssrc   = (int*)(sscr + 1024);            // [1024]

    const int tid = threadIdx.x;
    const int m0 = blockIdx.x * 128;
    const int wid = tid >> 5, lane = tid & 31;
    const int wm = wid >> 2, wn = wid & 3;
    const int g = lane >> 2, tg = lane & 3;

    // preload scores + src for this block's 128 nodes
    for (int idx = tid; idx < 1024; idx += 256) {
        long gidx = (long)m0 * 8 + idx;
        bool ok = (m0 + (idx >> 3)) < M;
        ssrc[idx] = ok ? src[gidx] : 0;
        sscr[idx] = ok ? scr[gidx] : 0.f;
    }
    __syncthreads();

    // gather-stage A: 2 passes, 4 threads per row, 32 cols per thread
#pragma unroll
    for (int pass = 0; pass < 2; pass++) {
        int r = pass * 64 + (tid >> 2);     // 0..127
        int cseg = (tid & 3) * 32;          // col offset (halves)
        float a[32];
#pragma unroll
        for (int q = 0; q < 32; q++) a[q] = 0.f;
        if (m0 + r < M) {
#pragma unroll
            for (int e = 0; e < 8; e++) {
                int   s  = ssrc[r * 8 + e];
                float sc = sscr[r * 8 + e];
                const uint4* p = (const uint4*)(nt + (size_t)s * 128 + cseg);
#pragma unroll
                for (int q4 = 0; q4 < 4; q4++) {
                    uint4 v = p[q4];
                    float2 f0 = u2f2(v.x), f1 = u2f2(v.y), f2 = u2f2(v.z), f3 = u2f2(v.w);
                    a[q4 * 8 + 0] += sc * f0.x; a[q4 * 8 + 1] += sc * f0.y;
                    a[q4 * 8 + 2] += sc * f1.x; a[q4 * 8 + 3] += sc * f1.y;
                    a[q4 * 8 + 4] += sc * f2.x; a[q4 * 8 + 5] += sc * f2.y;
                    a[q4 * 8 + 6] += sc * f3.x; a[q4 * 8 + 7] += sc * f3.y;
                }
            }
#pragma unroll
            for (int q = 0; q < 32; q++) a[q] = a[q] > 0.f ? a[q] : (expf(a[q]) - 1.f);
        }
        uint32_t* d = As + r * LDH + (cseg >> 1);
#pragma unroll
        for (int q = 0; q < 16; q++)
            d[q] = h2u(__floats2half2_rn(a[q * 2], a[q * 2 + 1]));
    }

#pragma unroll
    for (int t = 0; t < 3; t++) {
        if (t) __syncthreads();
        stage_h16<16>(Ws, Wihh + (size_t)t * 128 * 128, 128, 128, 128, LDH);
        __syncthreads();

        float c[4][4][4];
#pragma unroll
        for (int mt = 0; mt < 4; mt++)
#pragma unroll
            for (int nt_ = 0; nt_ < 4; nt_++)
#pragma unroll
                for (int r = 0; r < 4; r++) c[mt][nt_][r] = 0.f;

        mma_loop_h<8, LDH>(As, Ws, wm, wn, g, tg, c);

#pragma unroll
        for (int mt = 0; mt < 4; mt++) {
            int r0 = m0 + wm * 64 + mt * 16 + g;
#pragma unroll
            for (int nt_ = 0; nt_ < 4; nt_++) {
                int col = t * 128 + wn * 32 + nt_ * 8 + tg * 2;
                float b0 = __ldg(b_ih + col), b1 = __ldg(b_ih + col + 1);
                if (r0 < M)
                    *(__half2*)(gi + (size_t)r0 * 384 + col) =
                        __floats2half2_rn(c[mt][nt_][0] + b0, c[mt][nt_][1] + b1);
                if (r0 + 8 < M)
                    *(__half2*)(gi + (size_t)(r0 + 8) * 384 + col) =
                        __floats2half2_rn(c[mt][nt_][2] + b0, c[mt][nt_][3] + b1);
            }
        }
    }
}

// ---------------------------------------------------------------------------
// Edge kernel (split-K, fp16, BM=128, 2 CTAs/SM) — R13 config.
// ---------------------------------------------------------------------------
__global__ __launch_bounds__(256, 2)
void edge_kernel(const float* __restrict__ bond, const int* __restrict__ src,
                 const float* __restrict__ h1, const __half* __restrict__ P,
                 const __half* __restrict__ W2h, const float* __restrict__ Ww,
                 const float* __restrict__ bw, float* __restrict__ scr) {
    extern __shared__ uint32_t smu[];
    uint32_t* Xs   = smu;                              // [128][LDHB]
    uint32_t* Ws   = smu + 128 * LDHB;                 // [128][LDHB]
    float* slog    = (float*)(smu + 2 * 128 * LDHB);   // [4][128]
    float* sndot   = slog + 4 * 128;                   // [16]
    int*   ssrc    = (int*)(sndot + 16);               // [128]

    const int tid = threadIdx.x;
    const int nb = blockIdx.x * 16;
    const long eb = (long)blockIdx.x * 128;
    const int wid = tid >> 5, lane = tid & 31;
    const int wm = wid >> 2, wn = wid & 3;
    const int g = lane >> 2, tg = lane & 3;

    if (tid < 128) ssrc[tid] = src[eb + tid];

    // per-node h1 . Ww[0:128] + bw : 16 lanes per node
    {
        int gn = tid >> 4, l = tid & 15;
        const float* hr = h1 + (size_t)(nb + gn) * 128;
        float s = 0.f;
#pragma unroll
        for (int t = 0; t < 8; t++) s += hr[l + 16 * t] * Ww[l + 16 * t];
        s += __shfl_xor_sync(0xffffffffu, s, 1);
        s += __shfl_xor_sync(0xffffffffu, s, 2);
        s += __shfl_xor_sync(0xffffffffu, s, 4);
        s += __shfl_xor_sync(0xffffffffu, s, 8);
        if (l == 0) sndot[gn] = s + bw[0];
    }

    stage_h16<8>(Ws, W2h + 128, 192, 128, 128, LDHB);
    stage_h(Xs, bond + eb * 64, 64, 0, 128, 128, 16, LDHB);
    __syncthreads();

    float c[4][4][4];
#pragma unroll
    for (int mt = 0; mt < 4; mt++)
#pragma unroll
        for (int ntl = 0; ntl < 4; ntl++)
#pragma unroll
            for (int r = 0; r < 4; r++) c[mt][ntl][r] = 0.f;

    mma_loop_h<4, LDHB>(Xs, Ws, wm, wn, g, tg, c);

#pragma unroll
    for (int mt = 0; mt < 4; mt++) {
        int r0 = wm * 64 + mt * 16 + g;
        const __half2* p0r = (const __half2*)(P + (size_t)ssrc[r0] * 128);
        const __half2* p1r = (const __half2*)(P + (size_t)ssrc[r0 + 8] * 128);
        float s0 = 0.f, s1 = 0.f;
#pragma unroll
        for (int ntl = 0; ntl < 4; ntl++) {
            int col = wn * 32 + ntl * 8 + tg * 2;
            float w0 = __ldg(Ww + 128 + col), w1 = __ldg(Ww + 128 + col + 1);
            float2 pa = __half22float2(p0r[col >> 1]);
            float2 pb = __half22float2(p1r[col >> 1]);
            s0 += lrelu_f(c[mt][ntl][0] + pa.x) * w0 + lrelu_f(c[mt][ntl][1] + pa.y) * w1;
            s1 += lrelu_f(c[mt][ntl][2] + pb.x) * w0 + lrelu_f(c[mt][ntl][3] + pb.y) * w1;
        }
        s0 += __shfl_xor_sync(0xffffffffu, s0, 1);
        s0 += __shfl_xor_sync(0xffffffffu, s0, 2);
        s1 += __shfl_xor_sync(0xffffffffu, s1, 1);
        s1 += __shfl_xor_sync(0xffffffffu, s1, 2);
        if (tg == 0) {
            slog[wn * 128 + r0]     = s0;
            slog[wn * 128 + r0 + 8] = s1;
        }
    }
    __syncthreads();

    if (tid < 16) {
        float base = sndot[tid];
        float l[8];
        float m = -1e30f;
#pragma unroll
        for (int e = 0; e < 8; e++) {
            int i = tid * 8 + e;
            float v = slog[i] + slog[128 + i] + slog[256 + i] + slog[384 + i];
            v = lrelu_f(v + base);
            l[e] = v;
            m = fmaxf(m, v);
        }
        float ssum = 0.f;
#pragma unroll
        for (int e = 0; e < 8; e++) { l[e] = expf(l[e] - m); ssum += l[e]; }
        float inv = 1.f / ssum;
        float* so = scr + eb + tid * 8;
#pragma unroll
        for (int e = 0; e < 8; e++) so[e] = l[e] * inv;
    }
}

// ---------------------------------------------------------------------------
// GRU elementwise combine (gi/gh fp16, h1/out fp32). 8 cols per thread.
// ---------------------------------------------------------------------------
__global__ __launch_bounds__(256)
void gru_combine(const __half* __restrict__ gi, const __half* __restrict__ gh,
                 const float* __restrict__ h1, float* __restrict__ out) {
    int i = blockIdx.x * blockDim.x + threadIdx.x;
    if (i >= NN * 16) return;
    int n = i >> 4, c0 = (i & 15) * 8;
    const __half* gin = gi + (size_t)n * 384;
    const __half* ghn = gh + (size_t)n * 384;

    uint4 ir8 = *(const uint4*)(gin + c0);
    uint4 iz8 = *(const uint4*)(gin + 128 + c0);
    uint4 in8 = *(const uint4*)(gin + 256 + c0);
    uint4 hr8 = *(const uint4*)(ghn + c0);
    uint4 hz8 = *(const uint4*)(ghn + 128 + c0);
    uint4 hn8 = *(const uint4*)(ghn + 256 + c0);

    float irv[8], izv[8], inv_[8], hrv[8], hzv[8], hnv[8];
    {
        float2 t;
        t = u2f2(ir8.x); irv[0]=t.x; irv[1]=t.y;  t = u2f2(ir8.y); irv[2]=t.x; irv[3]=t.y;
        t = u2f2(ir8.z); irv[4]=t.x; irv[5]=t.y;  t = u2f2(ir8.w); irv[6]=t.x; irv[7]=t.y;
        t = u2f2(iz8.x); izv[0]=t.x; izv[1]=t.y;  t = u2f2(iz8.y); izv[2]=t.x; izv[3]=t.y;
        t = u2f2(iz8.z); izv[4]=t.x; izv[5]=t.y;  t = u2f2(iz8.w); izv[6]=t.x; izv[7]=t.y;
        t = u2f2(in8.x); inv_[0]=t.x; inv_[1]=t.y; t = u2f2(in8.y); inv_[2]=t.x; inv_[3]=t.y;
        t = u2f2(in8.z); inv_[4]=t.x; inv_[5]=t.y; t = u2f2(in8.w); inv_[6]=t.x; inv_[7]=t.y;
        t = u2f2(hr8.x); hrv[0]=t.x; hrv[1]=t.y;  t = u2f2(hr8.y); hrv[2]=t.x; hrv[3]=t.y;
        t = u2f2(hr8.z); hrv[4]=t.x; hrv[5]=t.y;  t = u2f2(hr8.w); hrv[6]=t.x; hrv[7]=t.y;
        t = u2f2(hz8.x); hzv[0]=t.x; hzv[1]=t.y;  t = u2f2(hz8.y); hzv[2]=t.x; hzv[3]=t.y;
        t = u2f2(hz8.z); hzv[4]=t.x; hzv[5]=t.y;  t = u2f2(hz8.w); hzv[6]=t.x; hzv[7]=t.y;
        t = u2f2(hn8.x); hnv[0]=t.x; hnv[1]=t.y;  t = u2f2(hn8.y); hnv[2]=t.x; hnv[3]=t.y;
        t = u2f2(hn8.z); hnv[4]=t.x; hnv[5]=t.y;  t = u2f2(hn8.w); hnv[6]=t.x; hnv[7]=t.y;
    }

    const float* h1r = h1 + (size_t)n * 128 + c0;
    float* orow = out + (size_t)n * 128 + c0;
    float4 h0 = *(const float4*)(h1r);
    float4 h1v = *(const float4*)(h1r + 4);
    float hv[8] = {h0.x, h0.y, h0.z, h0.w, h1v.x, h1v.y, h1v.z, h1v.w};
    float ov[8];
#pragma unroll
    for (int q = 0; q < 8; q++) {
        float r = 1.f / (1.f + expf(-(irv[q] + hrv[q])));
        float z = 1.f / (1.f + expf(-(izv[q] + hzv[q])));
        float nv = tanhf(inv_[q] + r * hnv[q]);
        ov[q] = (1.f - z) * nv + z * hv[q];
    }
    *(float4*)(orow)     = make_float4(ov[0], ov[1], ov[2], ov[3]);
    *(float4*)(orow + 4) = make_float4(ov[4], ov[5], ov[6], ov[7]);
}

// ---------------------------------------------------------------------------
extern "C" void kernel_launch(void* const* d_in, const int* in_sizes, int n_in,
                              void* d_out, int out_size) {
    const float* atom = (const float*)d_in[0];
    const float* bond = (const float*)d_in[1];
    const int*   src  = (const int*)d_in[2];
    // d_in[3] = dst (structurally e/8; unused)
    const float* W1   = (const float*)d_in[4];
    const float* b1   = (const float*)d_in[5];
    const float* W2   = (const float*)d_in[6];
    const float* b2   = (const float*)d_in[7];
    const float* Wa   = (const float*)d_in[8];
    const float* ba   = (const float*)d_in[9];
    const float* Ww   = (const float*)d_in[10];
    const float* bw   = (const float*)d_in[11];
    const float* W_ih = (const float*)d_in[12];
    const float* b_ih = (const float*)d_in[13];
    const float* W_hh = (const float*)d_in[14];
    const float* b_hh = (const float*)d_in[15];

    float* out = (float*)d_out;

    __half *nt, *P, *gi, *gh, *h1h, *W1h, *Wah, *W2h, *Wihh, *Whhh;
    float *scr, *h1fb;
    cudaGetSymbolAddress((void**)&nt,   g_nt);
    cudaGetSymbolAddress((void**)&P,    g_P);
    cudaGetSymbolAddress((void**)&gi,   g_gi);
    cudaGetSymbolAddress((void**)&gh,   g_gh);
    cudaGetSymbolAddress((void**)&h1h,  g_h1h);
    cudaGetSymbolAddress((void**)&scr,  g_scr);
    cudaGetSymbolAddress((void**)&h1fb, g_h1);
    cudaGetSymbolAddress((void**)&W1h,  g_W1h);
    cudaGetSymbolAddress((void**)&Wah,  g_Wah);
    cudaGetSymbolAddress((void**)&W2h,  g_W2h);
    cudaGetSymbolAddress((void**)&Wihh, g_Wihh);
    cudaGetSymbolAddress((void**)&Whhh, g_Whhh);

    float* h1 = (out_size >= 2 * NN * 128) ? (out + (size_t)NN * 128) : h1fb;

    const int GSM  = 2 * 128 * LDH * 4;                                  // 67584
    const int GISM = GSM + 1024 * 8;                                     // + scr/src
    const int ESM  = 2 * 128 * LDHB * 4 + (4 * 128 + 16) * 4 + 128 * 4;  // ~37.5 KB

    cudaFuncSetAttribute((tc_gemm<1, false, false, true>), cudaFuncAttributeMaxDynamicSharedMemorySize, GSM);
    cudaFuncSetAttribute((tc_gemm<0, false, true, false>), cudaFuncAttributeMaxDynamicSharedMemorySize, GSM);
    cudaFuncSetAttribute((tc_gemm<0, true, true, false>),  cudaFuncAttributeMaxDynamicSharedMemorySize, GSM);
    cudaFuncSetAttribute(gi_kernel,   cudaFuncAttributeMaxDynamicSharedMemorySize, GISM);
    cudaFuncSetAttribute(edge_kernel, cudaFuncAttributeMaxDynamicSharedMemorySize, ESM);

    static cudaStream_t s2 = nullptr, s3 = nullptr;
    static cudaEvent_t ev0 = nullptr, evP = nullptr, evH = nullptr;
    static cudaEvent_t evNT = nullptr, evGH = nullptr;
    if (!s2) {
        cudaStreamCreateWithFlags(&s2, cudaStreamNonBlocking);
        cudaStreamCreateWithFlags(&s3, cudaStreamNonBlocking);
        cudaEventCreateWithFlags(&ev0, cudaEventDisableTiming);
        cudaEventCreateWithFlags(&evP, cudaEventDisableTiming);
        cudaEventCreateWithFlags(&evH, cudaEventDisableTiming);
        cudaEventCreateWithFlags(&evNT, cudaEventDisableTiming);
        cudaEventCreateWithFlags(&evGH, cudaEventDisableTiming);
    }

    const int MB = (NN + 127) / 128;  // 782

    // 0) weight pre-convert, then fork
    wconvert<<<192, 256>>>(W1, Wa, W2, W_ih, W_hh);
    cudaEventRecord(ev0, 0);
    cudaStreamWaitEvent(s2, ev0, 0);
    cudaStreamWaitEvent(s3, ev0, 0);

    // main: h1 = lrelu(atom @ W1^T + b1) -> fp32 (output) + fp16 shadow
    tc_gemm<1, false, false, true><<<dim3(1, MB), 256, GSM>>>(atom, W1h, b1, h1, h1h, NN, 128, 128);
    cudaEventRecord(evH, 0);

    // s2: P = atom @ W2a^T + b2 -> fp16   (independent of h1)
    tc_gemm<0, false, true, false><<<dim3(1, MB), 256, GSM, s2>>>(atom, W2h, b2, P, nullptr, NN, 128, 192);
    cudaEventRecord(evP, s2);

    // s3: nt then gh (need only h1h; overlap the edge kernel)
    cudaStreamWaitEvent(s3, evH, 0);
    tc_gemm<0, true, true, false><<<dim3(1, MB), 256, GSM, s3>>>(h1h, Wah, ba, nt, nullptr, NN, 128, 128);
    cudaEventRecord(evNT, s3);
    tc_gemm<0, true, true, false><<<dim3(3, MB), 256, GSM, s3>>>(h1h, Whhh, b_hh, gh, nullptr, NN, 384, 128);
    cudaEventRecord(evGH, s3);

    // main: edge logits + softmax -> scores (needs h1 + P only)
    cudaStreamWaitEvent(0, evP, 0);
    edge_kernel<<<NN / 16, 256, ESM>>>(bond, src, h1, P, W2h, Ww, bw, scr);

    // main: gi with fused ctx gather (needs scores + nt)
    cudaStreamWaitEvent(0, evNT, 0);
    gi_kernel<<<MB, 256, GISM>>>(src, scr, nt, Wihh, b_ih, gi, NN);

    // main: combine (needs gi + gh)
    cudaStreamWaitEvent(0, evGH, 0);
    gru_combine<<<(NN * 16 + 255) / 256, 256>>>(gi, gh, h1, out);
}

// round 16
// speedup vs baseline: 1.0196x; 1.0196x over previous
#include <cuda_runtime.h>
#include <cuda_fp16.h>
#include <math.h>
#include <stdint.h>

#define NN 100000
#define LEAKY 0.2f

constexpr int LDH  = 66;   // u32 row stride for K=128 fp16 tiles (64 + 2 pad)
constexpr int LDHB = 34;   // u32 row stride for K=64  fp16 tiles (32 + 2 pad)

// ---------------- scratch (device globals; no allocation allowed) -----------
__device__ __half g_nt  [(size_t)NN * 128];
__device__ __half g_ctx [(size_t)NN * 128];
__device__ __half g_P   [(size_t)NN * 128];
__device__ __half g_h1h [(size_t)NN * 128];
__device__ __half g_gi  [(size_t)NN * 384];
__device__ __half g_gh  [(size_t)NN * 384];
__device__ float  g_h1  [(size_t)NN * 128];
__device__ float  g_scr [(size_t)NN * 8];
// fp16 weight copies
__device__ __half g_W1h [128 * 128];
__device__ __half g_Wah [128 * 128];
__device__ __half g_W2h [128 * 192];
__device__ __half g_Wihh[384 * 128];
__device__ __half g_Whhh[384 * 128];

__device__ __forceinline__ float lrelu_f(float x) { return x > 0.f ? x : LEAKY * x; }

__device__ __forceinline__ uint32_t h2u(__half2 h) {
    return *reinterpret_cast<uint32_t*>(&h);
}
__device__ __forceinline__ float2 u2f2(uint32_t u) {
    return __half22float2(*reinterpret_cast<__half2*>(&u));
}

__device__ __forceinline__ void mma_f16(float c[4], uint32_t a0, uint32_t a1,
                                        uint32_t a2, uint32_t a3,
                                        uint32_t b0, uint32_t b1) {
    asm volatile(
        "mma.sync.aligned.m16n8k16.row.col.f32.f16.f16.f32 "
        "{%0,%1,%2,%3}, {%4,%5,%6,%7}, {%8,%9}, {%0,%1,%2,%3};"
        : "+f"(c[0]), "+f"(c[1]), "+f"(c[2]), "+f"(c[3])
        : "r"(a0), "r"(a1), "r"(a2), "r"(a3), "r"(b0), "r"(b1));
}

// ---------------------------------------------------------------------------
__global__ void wconvert(const float* __restrict__ W1, const float* __restrict__ Wa,
                         const float* __restrict__ W2, const float* __restrict__ Wih,
                         const float* __restrict__ Whh) {
    int i = blockIdx.x * 256 + threadIdx.x;
    if (i < 16384) { g_W1h[i] = __float2half(W1[i]); g_Wah[i] = __float2half(Wa[i]); }
    if (i < 24576) g_W2h[i] = __float2half(W2[i]);
    if (i < 49152) { g_Wihh[i] = __float2half(Wih[i]); g_Whhh[i] = __float2half(Whh[i]); }
}

// ---------------------------------------------------------------------------
// Stage f32 [rows x (qk*4)] block as fp16 into smem u32 [.][ldh].
// ---------------------------------------------------------------------------
__device__ __forceinline__ void stage_h(uint32_t* __restrict__ dst,
                                        const float* __restrict__ srcp,
                                        int srcK, int koff,
                                        int rows_valid, int rows_total,
                                        int qk, int ldh) {
    const int tid = threadIdx.x;
    for (int idx = tid; idx < rows_total * qk; idx += blockDim.x) {
        int row = idx / qk;
        int q   = idx - row * qk;
        float4 v = make_float4(0.f, 0.f, 0.f, 0.f);
        if (row < rows_valid) v = *(const float4*)(srcp + (size_t)row * srcK + koff + q * 4);
        uint32_t* d = dst + row * ldh + q * 2;
        d[0] = h2u(__floats2half2_rn(v.x, v.y));
        d[1] = h2u(__floats2half2_rn(v.z, v.w));
    }
}

// Stage fp16 source directly: QK4 uint4 (=8 halves) per row.
template <int QK4>
__device__ __forceinline__ void stage_h16(uint32_t* __restrict__ dst,
                                          const __half* __restrict__ srcp,
                                          int srcK, int rows_valid,
                                          int rows_total, int ldh) {
    const int tid = threadIdx.x;
    for (int idx = tid; idx < rows_total * QK4; idx += blockDim.x) {
        int row = idx / QK4;
        int q   = idx - row * QK4;
        uint4 v = make_uint4(0u, 0u, 0u, 0u);
        if (row < rows_valid) v = *(const uint4*)(srcp + (size_t)row * srcK + q * 8);
        uint32_t* d = dst + row * ldh + q * 4;
        d[0] = v.x; d[1] = v.y; d[2] = v.z; d[3] = v.w;
    }
}

// ---------------------------------------------------------------------------
// Warp-tile fp16 mainloop. NKS k16 steps, 4 m16 x 4 n8 tiles per warp.
// ---------------------------------------------------------------------------
template <int NKS, int LDH_>
__device__ __forceinline__ void mma_loop_h(const uint32_t* __restrict__ As,
                                           const uint32_t* __restrict__ Ws,
                                           int wm, int wn, int g, int tg,
                                           float c[4][4][4]) {
#pragma unroll
    for (int ks = 0; ks < NKS; ks++) {
        uint32_t b[4][2];
#pragma unroll
        for (int nt = 0; nt < 4; nt++) {
            const uint32_t* bp = Ws + (wn * 32 + nt * 8 + g) * LDH_ + ks * 8 + tg;
            b[nt][0] = bp[0];
            b[nt][1] = bp[4];
        }
#pragma unroll
        for (int mt = 0; mt < 4; mt++) {
            const uint32_t* ap = As + (wm * 64 + mt * 16 + g) * LDH_ + ks * 8 + tg;
            uint32_t a0 = ap[0];
            uint32_t a1 = ap[8 * LDH_];
            uint32_t a2 = ap[4];
            uint32_t a3 = ap[8 * LDH_ + 4];
#pragma unroll
            for (int nt = 0; nt < 4; nt++)
                mma_f16(c[mt][nt], a0, a1, a2, a3, b[nt][0], b[nt][1]);
        }
    }
}

// ---------------------------------------------------------------------------
// Node GEMM (single n-tile): C[M x Nout] = act(A[M x 128] @ Wh^T + bias)
// AH: A fp16. CH: C fp16. DUP: also write fp16 copy to C2.
// ---------------------------------------------------------------------------
template <int ACT, bool AH, bool CH, bool DUP>
__global__ __launch_bounds__(256, 2)
void tc_gemm(const void* __restrict__ A_, const __half* __restrict__ Wh,
             const float* __restrict__ bias, void* __restrict__ C_,
             __half* __restrict__ C2, int M, int Nout, int wK) {
    extern __shared__ uint32_t smu[];
    uint32_t* As = smu;                 // [128][LDH]
    uint32_t* Ws = smu + 128 * LDH;     // [128][LDH]

    const int tid = threadIdx.x;
    const int m0 = blockIdx.y * 128;
    const int n0 = blockIdx.x * 128;
    const int wid = tid >> 5, lane = tid & 31;
    const int wm = wid >> 2, wn = wid & 3;
    const int g = lane >> 2, tg = lane & 3;

    if (AH) stage_h16<16>(As, (const __half*)A_ + (size_t)m0 * 128, 128, M - m0, 128, LDH);
    else    stage_h(As, (const float*)A_ + (size_t)m0 * 128, 128, 0, M - m0, 128, 32, LDH);
    stage_h16<16>(Ws, Wh + (size_t)n0 * wK, wK, 128, 128, LDH);
    __syncthreads();

    float c[4][4][4];
#pragma unroll
    for (int mt = 0; mt < 4; mt++)
#pragma unroll
        for (int nt = 0; nt < 4; nt++)
#pragma unroll
            for (int r = 0; r < 4; r++) c[mt][nt][r] = 0.f;

    mma_loop_h<8, LDH>(As, Ws, wm, wn, g, tg, c);

#pragma unroll
    for (int mt = 0; mt < 4; mt++) {
        int r0 = m0 + wm * 64 + mt * 16 + g;
#pragma unroll
        for (int nt = 0; nt < 4; nt++) {
            int col = n0 + wn * 32 + nt * 8 + tg * 2;
            float b0 = __ldg(bias + col), b1 = __ldg(bias + col + 1);
            float v0 = c[mt][nt][0] + b0, v1 = c[mt][nt][1] + b1;
            float v2 = c[mt][nt][2] + b0, v3 = c[mt][nt][3] + b1;
            if (ACT == 1) { v0 = lrelu_f(v0); v1 = lrelu_f(v1); v2 = lrelu_f(v2); v3 = lrelu_f(v3); }
            if (CH) {
                __half* C = (__half*)C_;
                if (r0 < M)     *(__half2*)(C + (size_t)r0 * Nout + col)       = __floats2half2_rn(v0, v1);
                if (r0 + 8 < M) *(__half2*)(C + (size_t)(r0 + 8) * Nout + col) = __floats2half2_rn(v2, v3);
            } else {
                float* C = (float*)C_;
                if (r0 < M)     *(float2*)(C + (size_t)r0 * Nout + col)       = make_float2(v0, v1);
                if (r0 + 8 < M) *(float2*)(C + (size_t)(r0 + 8) * Nout + col) = make_float2(v2, v3);
            }
            if (DUP) {
                if (r0 < M)     *(__half2*)(C2 + (size_t)r0 * Nout + col)       = __floats2half2_rn(v0, v1);
                if (r0 + 8 < M) *(__half2*)(C2 + (size_t)(r0 + 8) * Nout + col) = __floats2half2_rn(v2, v3);
            }
        }
    }
}

// ---------------------------------------------------------------------------
// Fused h1 + P kernel: stage atom once (A-resident), two W tiles.
//   h1 = lrelu(atom @ W1^T + b1) -> fp32 out + fp16 shadow
//   P  = atom @ W2a^T + b2       -> fp16
// ---------------------------------------------------------------------------
__global__ __launch_bounds__(256, 2)
void hp_kernel(const float* __restrict__ atom, const __half* __restrict__ W1h,
               const float* __restrict__ b1, const __half* __restrict__ W2h,
               const float* __restrict__ b2, float* __restrict__ h1,
               __half* __restrict__ h1h, __half* __restrict__ P, int M) {
    extern __shared__ uint32_t smu[];
    uint32_t* As = smu;                 // [128][LDH]
    uint32_t* Ws = smu + 128 * LDH;     // [128][LDH]

    const int tid = threadIdx.x;
    const int m0 = blockIdx.x * 128;
    const int wid = tid >> 5, lane = tid & 31;
    const int wm = wid >> 2, wn = wid & 3;
    const int g = lane >> 2, tg = lane & 3;

    stage_h(As, atom + (size_t)m0 * 128, 128, 0, M - m0, 128, 32, LDH);

    float c[4][4][4];

#pragma unroll
    for (int t = 0; t < 2; t++) {
        if (t) __syncthreads();
        if (t == 0) stage_h16<16>(Ws, W1h, 128, 128, 128, LDH);
        else        stage_h16<16>(Ws, W2h, 192, 128, 128, LDH);
        __syncthreads();

#pragma unroll
        for (int mt = 0; mt < 4; mt++)
#pragma unroll
            for (int nt = 0; nt < 4; nt++)
#pragma unroll
                for (int r = 0; r < 4; r++) c[mt][nt][r] = 0.f;

        mma_loop_h<8, LDH>(As, Ws, wm, wn, g, tg, c);

        const float* bias = (t == 0) ? b1 : b2;
#pragma unroll
        for (int mt = 0; mt < 4; mt++) {
            int r0 = m0 + wm * 64 + mt * 16 + g;
#pragma unroll
            for (int nt = 0; nt < 4; nt++) {
                int col = wn * 32 + nt * 8 + tg * 2;
                float b0 = __ldg(bias + col), bb1 = __ldg(bias + col + 1);
                float v0 = c[mt][nt][0] + b0, v1 = c[mt][nt][1] + bb1;
                float v2 = c[mt][nt][2] + b0, v3 = c[mt][nt][3] + bb1;
                if (t == 0) {
                    v0 = lrelu_f(v0); v1 = lrelu_f(v1); v2 = lrelu_f(v2); v3 = lrelu_f(v3);
                    if (r0 < M) {
                        *(float2*)(h1 + (size_t)r0 * 128 + col) = make_float2(v0, v1);
                        *(__half2*)(h1h + (size_t)r0 * 128 + col) = __floats2half2_rn(v0, v1);
                    }
                    if (r0 + 8 < M) {
                        *(float2*)(h1 + (size_t)(r0 + 8) * 128 + col) = make_float2(v2, v3);
                        *(__half2*)(h1h + (size_t)(r0 + 8) * 128 + col) = __floats2half2_rn(v2, v3);
                    }
                } else {
                    if (r0 < M)     *(__half2*)(P + (size_t)r0 * 128 + col)       = __floats2half2_rn(v0, v1);
                    if (r0 + 8 < M) *(__half2*)(P + (size_t)(r0 + 8) * 128 + col) = __floats2half2_rn(v2, v3);
                }
            }
        }
    }
}

// ---------------------------------------------------------------------------
// Edge kernel (split-K, fp16, BM=128, 2 CTAs/SM) — R13 config.
// ---------------------------------------------------------------------------
__global__ __launch_bounds__(256, 2)
void edge_kernel(const float* __restrict__ bond, const int* __restrict__ src,
                 const float* __restrict__ h1, const __half* __restrict__ P,
                 const __half* __restrict__ W2h, const float* __restrict__ Ww,
                 const float* __restrict__ bw, float* __restrict__ scr) {
    extern __shared__ uint32_t smu[];
    uint32_t* Xs   = smu;                              // [128][LDHB]
    uint32_t* Ws   = smu + 128 * LDHB;                 // [128][LDHB]
    float* slog    = (float*)(smu + 2 * 128 * LDHB);   // [4][128]
    float* sndot   = slog + 4 * 128;                   // [16]
    int*   ssrc    = (int*)(sndot + 16);               // [128]

    const int tid = threadIdx.x;
    const int nb = blockIdx.x * 16;
    const long eb = (long)blockIdx.x * 128;
    const int wid = tid >> 5, lane = tid & 31;
    const int wm = wid >> 2, wn = wid & 3;
    const int g = lane >> 2, tg = lane & 3;

    if (tid < 128) ssrc[tid] = src[eb + tid];

    // per-node h1 . Ww[0:128] + bw : 16 lanes per node
    {
        int gn = tid >> 4, l = tid & 15;
        const float* hr = h1 + (size_t)(nb + gn) * 128;
        float s = 0.f;
#pragma unroll
        for (int t = 0; t < 8; t++) s += hr[l + 16 * t] * Ww[l + 16 * t];
        s += __shfl_xor_sync(0xffffffffu, s, 1);
        s += __shfl_xor_sync(0xffffffffu, s, 2);
        s += __shfl_xor_sync(0xffffffffu, s, 4);
        s += __shfl_xor_sync(0xffffffffu, s, 8);
        if (l == 0) sndot[gn] = s + bw[0];
    }

    stage_h16<8>(Ws, W2h + 128, 192, 128, 128, LDHB);
    stage_h(Xs, bond + eb * 64, 64, 0, 128, 128, 16, LDHB);
    __syncthreads();

    float c[4][4][4];
#pragma unroll
    for (int mt = 0; mt < 4; mt++)
#pragma unroll
        for (int ntl = 0; ntl < 4; ntl++)
#pragma unroll
            for (int r = 0; r < 4; r++) c[mt][ntl][r] = 0.f;

    mma_loop_h<4, LDHB>(Xs, Ws, wm, wn, g, tg, c);

#pragma unroll
    for (int mt = 0; mt < 4; mt++) {
        int r0 = wm * 64 + mt * 16 + g;
        const __half2* p0r = (const __half2*)(P + (size_t)ssrc[r0] * 128);
        const __half2* p1r = (const __half2*)(P + (size_t)ssrc[r0 + 8] * 128);
        float s0 = 0.f, s1 = 0.f;
#pragma unroll
        for (int ntl = 0; ntl < 4; ntl++) {
            int col = wn * 32 + ntl * 8 + tg * 2;
            float w0 = __ldg(Ww + 128 + col), w1 = __ldg(Ww + 128 + col + 1);
            float2 pa = __half22float2(p0r[col >> 1]);
            float2 pb = __half22float2(p1r[col >> 1]);
            s0 += lrelu_f(c[mt][ntl][0] + pa.x) * w0 + lrelu_f(c[mt][ntl][1] + pa.y) * w1;
            s1 += lrelu_f(c[mt][ntl][2] + pb.x) * w0 + lrelu_f(c[mt][ntl][3] + pb.y) * w1;
        }
        s0 += __shfl_xor_sync(0xffffffffu, s0, 1);
        s0 += __shfl_xor_sync(0xffffffffu, s0, 2);
        s1 += __shfl_xor_sync(0xffffffffu, s1, 1);
        s1 += __shfl_xor_sync(0xffffffffu, s1, 2);
        if (tg == 0) {
            slog[wn * 128 + r0]     = s0;
            slog[wn * 128 + r0 + 8] = s1;
        }
    }
    __syncthreads();

    if (tid < 16) {
        float base = sndot[tid];
        float l[8];
        float m = -1e30f;
#pragma unroll
        for (int e = 0; e < 8; e++) {
            int i = tid * 8 + e;
            float v = slog[i] + slog[128 + i] + slog[256 + i] + slog[384 + i];
            v = lrelu_f(v + base);
            l[e] = v;
            m = fmaxf(m, v);
        }
        float ssum = 0.f;
#pragma unroll
        for (int e = 0; e < 8; e++) { l[e] = expf(l[e] - m); ssum += l[e]; }
        float inv = 1.f / ssum;
        float* so = scr + eb + tid * 8;
#pragma unroll
        for (int e = 0; e < 8; e++) so[e] = l[e] * inv;
    }
}

// ---------------------------------------------------------------------------
// Context gather: ctx[n] = elu( sum_e scr[n,e] * nt[src[n,e]] )  (fp16 nt/ctx)
// ---------------------------------------------------------------------------
__global__ __launch_bounds__(256)
void ctx_gather(const int* __restrict__ src, const float* __restrict__ scr,
                const __half* __restrict__ nt, __half* __restrict__ ctx) {
    const int tid = threadIdx.x;
    const int lane = tid & 31;
    const int gn = blockIdx.x * 16 + (tid >> 4);
    const int l = tid & 15;

    int   se8 = 0;
    float sc8 = 0.f;
    if ((lane & 15) < 8) {
        se8 = src[(size_t)gn * 8 + (lane & 15)];
        sc8 = scr[(size_t)gn * 8 + (lane & 15)];
    }

    float a[8];
#pragma unroll
    for (int q = 0; q < 8; q++) a[q] = 0.f;

#pragma unroll
    for (int e = 0; e < 8; e++) {
        int   sl = (lane & 16) | e;
        int   sidx = __shfl_sync(0xffffffffu, se8, sl, 32);
        float sc   = __shfl_sync(0xffffffffu, sc8, sl, 32);
        uint4 v = *(const uint4*)(nt + (size_t)sidx * 128 + l * 8);
        float2 f0 = u2f2(v.x), f1 = u2f2(v.y), f2 = u2f2(v.z), f3 = u2f2(v.w);
        a[0] += sc * f0.x; a[1] += sc * f0.y; a[2] += sc * f1.x; a[3] += sc * f1.y;
        a[4] += sc * f2.x; a[5] += sc * f2.y; a[6] += sc * f3.x; a[7] += sc * f3.y;
    }
#pragma unroll
    for (int q = 0; q < 8; q++) a[q] = a[q] > 0.f ? a[q] : (expf(a[q]) - 1.f);
    uint4 o;
    o.x = h2u(__floats2half2_rn(a[0], a[1]));
    o.y = h2u(__floats2half2_rn(a[2], a[3]));
    o.z = h2u(__floats2half2_rn(a[4], a[5]));
    o.w = h2u(__floats2half2_rn(a[6], a[7]));
    *(uint4*)(ctx + (size_t)gn * 128 + l * 8) = o;
}

// ---------------------------------------------------------------------------
// GRU elementwise combine (gi/gh fp16, h1/out fp32). 8 cols per thread.
// ---------------------------------------------------------------------------
__global__ __launch_bounds__(256)
void gru_combine(const __half* __restrict__ gi, const __half* __restrict__ gh,
                 const float* __restrict__ h1, float* __restrict__ out) {
    int i = blockIdx.x * blockDim.x + threadIdx.x;
    if (i >= NN * 16) return;
    int n = i >> 4, c0 = (i & 15) * 8;
    const __half* gin = gi + (size_t)n * 384;
    const __half* ghn = gh + (size_t)n * 384;

    uint4 ir8 = *(const uint4*)(gin + c0);
    uint4 iz8 = *(const uint4*)(gin + 128 + c0);
    uint4 in8 = *(const uint4*)(gin + 256 + c0);
    uint4 hr8 = *(const uint4*)(ghn + c0);
    uint4 hz8 = *(const uint4*)(ghn + 128 + c0);
    uint4 hn8 = *(const uint4*)(ghn + 256 + c0);

    float irv[8], izv[8], inv_[8], hrv[8], hzv[8], hnv[8];
    {
        float2 t;
        t = u2f2(ir8.x); irv[0]=t.x; irv[1]=t.y;  t = u2f2(ir8.y); irv[2]=t.x; irv[3]=t.y;
        t = u2f2(ir8.z); irv[4]=t.x; irv[5]=t.y;  t = u2f2(ir8.w); irv[6]=t.x; irv[7]=t.y;
        t = u2f2(iz8.x); izv[0]=t.x; izv[1]=t.y;  t = u2f2(iz8.y); izv[2]=t.x; izv[3]=t.y;
        t = u2f2(iz8.z); izv[4]=t.x; izv[5]=t.y;  t = u2f2(iz8.w); izv[6]=t.x; izv[7]=t.y;
        t = u2f2(in8.x); inv_[0]=t.x; inv_[1]=t.y; t = u2f2(in8.y); inv_[2]=t.x; inv_[3]=t.y;
        t = u2f2(in8.z); inv_[4]=t.x; inv_[5]=t.y; t = u2f2(in8.w); inv_[6]=t.x; inv_[7]=t.y;
        t = u2f2(hr8.x); hrv[0]=t.x; hrv[1]=t.y;  t = u2f2(hr8.y); hrv[2]=t.x; hrv[3]=t.y;
        t = u2f2(hr8.z); hrv[4]=t.x; hrv[5]=t.y;  t = u2f2(hr8.w); hrv[6]=t.x; hrv[7]=t.y;
        t = u2f2(hz8.x); hzv[0]=t.x; hzv[1]=t.y;  t = u2f2(hz8.y); hzv[2]=t.x; hzv[3]=t.y;
        t = u2f2(hz8.z); hzv[4]=t.x; hzv[5]=t.y;  t = u2f2(hz8.w); hzv[6]=t.x; hzv[7]=t.y;
        t = u2f2(hn8.x); hnv[0]=t.x; hnv[1]=t.y;  t = u2f2(hn8.y); hnv[2]=t.x; hnv[3]=t.y;
        t = u2f2(hn8.z); hnv[4]=t.x; hnv[5]=t.y;  t = u2f2(hn8.w); hnv[6]=t.x; hnv[7]=t.y;
    }

    const float* h1r = h1 + (size_t)n * 128 + c0;
    float* orow = out + (size_t)n * 128 + c0;
    float4 h0 = *(const float4*)(h1r);
    float4 h1v = *(const float4*)(h1r + 4);
    float hv[8] = {h0.x, h0.y, h0.z, h0.w, h1v.x, h1v.y, h1v.z, h1v.w};
    float ov[8];
#pragma unroll
    for (int q = 0; q < 8; q++) {
        float r = 1.f / (1.f + expf(-(irv[q] + hrv[q])));
        float z = 1.f / (1.f + expf(-(izv[q] + hzv[q])));
        float nv = tanhf(inv_[q] + r * hnv[q]);
        ov[q] = (1.f - z) * nv + z * hv[q];
    }
    *(float4*)(orow)     = make_float4(ov[0], ov[1], ov[2], ov[3]);
    *(float4*)(orow + 4) = make_float4(ov[4], ov[5], ov[6], ov[7]);
}

// ---------------------------------------------------------------------------
extern "C" void kernel_launch(void* const* d_in, const int* in_sizes, int n_in,
                              void* d_out, int out_size) {
    const float* atom = (const float*)d_in[0];
    const float* bond = (const float*)d_in[1];
    const int*   src  = (const int*)d_in[2];
    // d_in[3] = dst (structurally e/8; unused)
    const float* W1   = (const float*)d_in[4];
    const float* b1   = (const float*)d_in[5];
    const float* W2   = (const float*)d_in[6];
    const float* b2   = (const float*)d_in[7];
    const float* Wa   = (const float*)d_in[8];
    const float* ba   = (const float*)d_in[9];
    const float* Ww   = (const float*)d_in[10];
    const float* bw   = (const float*)d_in[11];
    const float* W_ih = (const float*)d_in[12];
    const float* b_ih = (const float*)d_in[13];
    const float* W_hh = (const float*)d_in[14];
    const float* b_hh = (const float*)d_in[15];

    float* out = (float*)d_out;

    __half *nt, *ctx, *P, *gi, *gh, *h1h, *W1h, *Wah, *W2h, *Wihh, *Whhh;
    float *scr, *h1fb;
    cudaGetSymbolAddress((void**)&nt,   g_nt);
    cudaGetSymbolAddress((void**)&ctx,  g_ctx);
    cudaGetSymbolAddress((void**)&P,    g_P);
    cudaGetSymbolAddress((void**)&gi,   g_gi);
    cudaGetSymbolAddress((void**)&gh,   g_gh);
    cudaGetSymbolAddress((void**)&h1h,  g_h1h);
    cudaGetSymbolAddress((void**)&scr,  g_scr);
    cudaGetSymbolAddress((void**)&h1fb, g_h1);
    cudaGetSymbolAddress((void**)&W1h,  g_W1h);
    cudaGetSymbolAddress((void**)&Wah,  g_Wah);
    cudaGetSymbolAddress((void**)&W2h,  g_W2h);
    cudaGetSymbolAddress((void**)&Wihh, g_Wihh);
    cudaGetSymbolAddress((void**)&Whhh, g_Whhh);

    float* h1 = (out_size >= 2 * NN * 128) ? (out + (size_t)NN * 128) : h1fb;

    const int GSM = 2 * 128 * LDH * 4;                                  // 67584
    const int ESM = 2 * 128 * LDHB * 4 + (4 * 128 + 16) * 4 + 128 * 4;  // ~37.5 KB

    cudaFuncSetAttribute(hp_kernel, cudaFuncAttributeMaxDynamicSharedMemorySize, GSM);
    cudaFuncSetAttribute((tc_gemm<0, true, true, false>), cudaFuncAttributeMaxDynamicSharedMemorySize, GSM);
    cudaFuncSetAttribute(edge_kernel, cudaFuncAttributeMaxDynamicSharedMemorySize, ESM);

    static cudaStream_t s3 = nullptr;
    static cudaEvent_t evH = nullptr, evNT = nullptr, evGH = nullptr;
    if (!s3) {
        cudaStreamCreateWithFlags(&s3, cudaStreamNonBlocking);
        cudaEventCreateWithFlags(&evH, cudaEventDisableTiming);
        cudaEventCreateWithFlags(&evNT, cudaEventDisableTiming);
        cudaEventCreateWithFlags(&evGH, cudaEventDisableTiming);
    }

    const int MB = (NN + 127) / 128;  // 782

    // 0) weight pre-convert
    wconvert<<<192, 256>>>(W1, Wa, W2, W_ih, W_hh);

    // main: fused h1 + P (atom staged once)
    hp_kernel<<<MB, 256, GSM>>>(atom, W1h, b1, W2h, b2, h1, h1h, P, NN);
    cudaEventRecord(evH, 0);

    // s3: nt then gh (need only h1h; overlap the edge kernel)
    cudaStreamWaitEvent(s3, evH, 0);
    tc_gemm<0, true, true, false><<<dim3(1, MB), 256, GSM, s3>>>(h1h, Wah, ba, nt, nullptr, NN, 128, 128);
    cudaEventRecord(evNT, s3);
    tc_gemm<0, true, true, false><<<dim3(3, MB), 256, GSM, s3>>>(h1h, Whhh, b_hh, gh, nullptr, NN, 384, 128);
    cudaEventRecord(evGH, s3);

    // main: edge logits + softmax -> scores (needs h1 + P only)
    edge_kernel<<<NN / 16, 256, ESM>>>(bond, src, h1, P, W2h, Ww, bw, scr);

    // main: ctx = elu(weighted gather of nt)
    cudaStreamWaitEvent(0, evNT, 0);
    ctx_gather<<<NN / 16, 256>>>(src, scr, nt, ctx);

    // main: gi = ctx @ W_ih^T + b_ih -> fp16
    tc_gemm<0, true, true, false><<<dim3(3, MB), 256, GSM>>>(ctx, Wihh, b_ih, gi, nullptr, NN, 384, 128);

    // main: combine (needs gi + gh)
    cudaStreamWaitEvent(0, evGH, 0);
    gru_combine<<<(NN * 16 + 255) / 256, 256>>>(gi, gh, h1, out);
}

// round 17
// speedup vs baseline: 1.0479x; 1.0278x over previous
#include <cuda_runtime.h>
#include <cuda_fp16.h>
#include <math.h>
#include <stdint.h>

#define NN 100000
#define LEAKY 0.2f

constexpr int LDH  = 66;   // u32 row stride for K=128 fp16 tiles (64 + 2 pad)
constexpr int LDHB = 34;   // u32 row stride for K=64  fp16 tiles (32 + 2 pad)

// ---------------- scratch (device globals; no allocation allowed) -----------
__device__ __half g_nt  [(size_t)NN * 128];
__device__ __half g_ctx [(size_t)NN * 128];
__device__ __half g_P   [(size_t)NN * 128];
__device__ __half g_h1h [(size_t)NN * 128];
__device__ __half g_gi  [(size_t)NN * 384];
__device__ __half g_gh  [(size_t)NN * 384];
__device__ float  g_h1  [(size_t)NN * 128];
__device__ float  g_scr [(size_t)NN * 8];
// fp16 weight copies
__device__ __half g_W1h [128 * 128];
__device__ __half g_Wah [128 * 128];
__device__ __half g_W2h [128 * 192];
__device__ __half g_Wihh[384 * 128];
__device__ __half g_Whhh[384 * 128];

__device__ __forceinline__ float lrelu_f(float x) { return x > 0.f ? x : LEAKY * x; }

__device__ __forceinline__ uint32_t h2u(__half2 h) {
    return *reinterpret_cast<uint32_t*>(&h);
}
__device__ __forceinline__ float2 u2f2(uint32_t u) {
    return __half22float2(*reinterpret_cast<__half2*>(&u));
}

__device__ __forceinline__ void mma_f16(float c[4], uint32_t a0, uint32_t a1,
                                        uint32_t a2, uint32_t a3,
                                        uint32_t b0, uint32_t b1) {
    asm volatile(
        "mma.sync.aligned.m16n8k16.row.col.f32.f16.f16.f32 "
        "{%0,%1,%2,%3}, {%4,%5,%6,%7}, {%8,%9}, {%0,%1,%2,%3};"
        : "+f"(c[0]), "+f"(c[1]), "+f"(c[2]), "+f"(c[3])
        : "r"(a0), "r"(a1), "r"(a2), "r"(a3), "r"(b0), "r"(b1));
}

// ---------------------------------------------------------------------------
__global__ void wconvert(const float* __restrict__ W1, const float* __restrict__ Wa,
                         const float* __restrict__ W2, const float* __restrict__ Wih,
                         const float* __restrict__ Whh) {
    int i = blockIdx.x * 256 + threadIdx.x;
    if (i < 16384) { g_W1h[i] = __float2half(W1[i]); g_Wah[i] = __float2half(Wa[i]); }
    if (i < 24576) g_W2h[i] = __float2half(W2[i]);
    if (i < 49152) { g_Wihh[i] = __float2half(Wih[i]); g_Whhh[i] = __float2half(Whh[i]); }
}

// ---------------------------------------------------------------------------
// Stage f32 [rows x (qk*4)] block as fp16 into smem u32 [.][ldh].
// ---------------------------------------------------------------------------
__device__ __forceinline__ void stage_h(uint32_t* __restrict__ dst,
                                        const float* __restrict__ srcp,
                                        int srcK, int koff,
                                        int rows_valid, int rows_total,
                                        int qk, int ldh) {
    const int tid = threadIdx.x;
    for (int idx = tid; idx < rows_total * qk; idx += blockDim.x) {
        int row = idx / qk;
        int q   = idx - row * qk;
        float4 v = make_float4(0.f, 0.f, 0.f, 0.f);
        if (row < rows_valid) v = *(const float4*)(srcp + (size_t)row * srcK + koff + q * 4);
        uint32_t* d = dst + row * ldh + q * 2;
        d[0] = h2u(__floats2half2_rn(v.x, v.y));
        d[1] = h2u(__floats2half2_rn(v.z, v.w));
    }
}

// Stage fp16 source directly: QK4 uint4 (=8 halves) per row.
template <int QK4>
__device__ __forceinline__ void stage_h16(uint32_t* __restrict__ dst,
                                          const __half* __restrict__ srcp,
                                          int srcK, int rows_valid,
                                          int rows_total, int ldh) {
    const int tid = threadIdx.x;
    for (int idx = tid; idx < rows_total * QK4; idx += blockDim.x) {
        int row = idx / QK4;
        int q   = idx - row * QK4;
        uint4 v = make_uint4(0u, 0u, 0u, 0u);
        if (row < rows_valid) v = *(const uint4*)(srcp + (size_t)row * srcK + q * 8);
        uint32_t* d = dst + row * ldh + q * 4;
        d[0] = v.x; d[1] = v.y; d[2] = v.z; d[3] = v.w;
    }
}

// ---------------------------------------------------------------------------
// Warp-tile fp16 mainloop. NKS k16 steps, 4 m16 x 4 n8 tiles per warp.
// ---------------------------------------------------------------------------
template <int NKS, int LDH_>
__device__ __forceinline__ void mma_loop_h(const uint32_t* __restrict__ As,
                                           const uint32_t* __restrict__ Ws,
                                           int wm, int wn, int g, int tg,
                                           float c[4][4][4]) {
#pragma unroll
    for (int ks = 0; ks < NKS; ks++) {
        uint32_t b[4][2];
#pragma unroll
        for (int nt = 0; nt < 4; nt++) {
            const uint32_t* bp = Ws + (wn * 32 + nt * 8 + g) * LDH_ + ks * 8 + tg;
            b[nt][0] = bp[0];
            b[nt][1] = bp[4];
        }
#pragma unroll
        for (int mt = 0; mt < 4; mt++) {
            const uint32_t* ap = As + (wm * 64 + mt * 16 + g) * LDH_ + ks * 8 + tg;
            uint32_t a0 = ap[0];
            uint32_t a1 = ap[8 * LDH_];
            uint32_t a2 = ap[4];
            uint32_t a3 = ap[8 * LDH_ + 4];
#pragma unroll
            for (int nt = 0; nt < 4; nt++)
                mma_f16(c[mt][nt], a0, a1, a2, a3, b[nt][0], b[nt][1]);
        }
    }
}

// ---------------------------------------------------------------------------
// Node GEMM with NT n-tiles (A staged once, resident):
//   C[M x NT*128] = act(A[M x 128] @ Wh(t)^T + bias)
// AH: A fp16. CH: C fp16. DUP: also write fp16 copy to C2 (NT=1 only).
// ---------------------------------------------------------------------------
template <int ACT, bool AH, bool CH, bool DUP, int NT>
__global__ __launch_bounds__(256, 2)
void tc_gemm(const void* __restrict__ A_, const __half* __restrict__ Wh,
             const float* __restrict__ bias, void* __restrict__ C_,
             __half* __restrict__ C2, int M, int wK) {
    extern __shared__ uint32_t smu[];
    uint32_t* As = smu;                 // [128][LDH]
    uint32_t* Ws = smu + 128 * LDH;     // [128][LDH]

    const int tid = threadIdx.x;
    const int m0 = blockIdx.x * 128;
    const int Nout = NT * 128;
    const int wid = tid >> 5, lane = tid & 31;
    const int wm = wid >> 2, wn = wid & 3;
    const int g = lane >> 2, tg = lane & 3;

    if (AH) stage_h16<16>(As, (const __half*)A_ + (size_t)m0 * 128, 128, M - m0, 128, LDH);
    else    stage_h(As, (const float*)A_ + (size_t)m0 * 128, 128, 0, M - m0, 128, 32, LDH);

#pragma unroll
    for (int t = 0; t < NT; t++) {
        if (t) __syncthreads();
        stage_h16<16>(Ws, Wh + (size_t)t * 128 * wK, wK, 128, 128, LDH);
        __syncthreads();

        float c[4][4][4];
#pragma unroll
        for (int mt = 0; mt < 4; mt++)
#pragma unroll
            for (int nt = 0; nt < 4; nt++)
#pragma unroll
                for (int r = 0; r < 4; r++) c[mt][nt][r] = 0.f;

        mma_loop_h<8, LDH>(As, Ws, wm, wn, g, tg, c);

#pragma unroll
        for (int mt = 0; mt < 4; mt++) {
            int r0 = m0 + wm * 64 + mt * 16 + g;
#pragma unroll
            for (int nt = 0; nt < 4; nt++) {
                int col = t * 128 + wn * 32 + nt * 8 + tg * 2;
                float b0 = __ldg(bias + col), b1 = __ldg(bias + col + 1);
                float v0 = c[mt][nt][0] + b0, v1 = c[mt][nt][1] + b1;
                float v2 = c[mt][nt][2] + b0, v3 = c[mt][nt][3] + b1;
                if (ACT == 1) { v0 = lrelu_f(v0); v1 = lrelu_f(v1); v2 = lrelu_f(v2); v3 = lrelu_f(v3); }
                if (CH) {
                    __half* C = (__half*)C_;
                    if (r0 < M)     *(__half2*)(C + (size_t)r0 * Nout + col)       = __floats2half2_rn(v0, v1);
                    if (r0 + 8 < M) *(__half2*)(C + (size_t)(r0 + 8) * Nout + col) = __floats2half2_rn(v2, v3);
                } else {
                    float* C = (float*)C_;
                    if (r0 < M)     *(float2*)(C + (size_t)r0 * Nout + col)       = make_float2(v0, v1);
                    if (r0 + 8 < M) *(float2*)(C + (size_t)(r0 + 8) * Nout + col) = make_float2(v2, v3);
                }
                if (DUP) {
                    if (r0 < M)     *(__half2*)(C2 + (size_t)r0 * Nout + col)       = __floats2half2_rn(v0, v1);
                    if (r0 + 8 < M) *(__half2*)(C2 + (size_t)(r0 + 8) * Nout + col) = __floats2half2_rn(v2, v3);
                }
            }
        }
    }
}

// ---------------------------------------------------------------------------
// Edge kernel (split-K, fp16, BM=128, 2 CTAs/SM) — R13 config.
// ---------------------------------------------------------------------------
__global__ __launch_bounds__(256, 2)
void edge_kernel(const float* __restrict__ bond, const int* __restrict__ src,
                 const float* __restrict__ h1, const __half* __restrict__ P,
                 const __half* __restrict__ W2h, const float* __restrict__ Ww,
                 const float* __restrict__ bw, float* __restrict__ scr) {
    extern __shared__ uint32_t smu[];
    uint32_t* Xs   = smu;                              // [128][LDHB]
    uint32_t* Ws   = smu + 128 * LDHB;                 // [128][LDHB]
    float* slog    = (float*)(smu + 2 * 128 * LDHB);   // [4][128]
    float* sndot   = slog + 4 * 128;                   // [16]
    int*   ssrc    = (int*)(sndot + 16);               // [128]

    const int tid = threadIdx.x;
    const int nb = blockIdx.x * 16;
    const long eb = (long)blockIdx.x * 128;
    const int wid = tid >> 5, lane = tid & 31;
    const int wm = wid >> 2, wn = wid & 3;
    const int g = lane >> 2, tg = lane & 3;

    if (tid < 128) ssrc[tid] = src[eb + tid];

    // per-node h1 . Ww[0:128] + bw : 16 lanes per node
    {
        int gn = tid >> 4, l = tid & 15;
        const float* hr = h1 + (size_t)(nb + gn) * 128;
        float s = 0.f;
#pragma unroll
        for (int t = 0; t < 8; t++) s += hr[l + 16 * t] * Ww[l + 16 * t];
        s += __shfl_xor_sync(0xffffffffu, s, 1);
        s += __shfl_xor_sync(0xffffffffu, s, 2);
        s += __shfl_xor_sync(0xffffffffu, s, 4);
        s += __shfl_xor_sync(0xffffffffu, s, 8);
        if (l == 0) sndot[gn] = s + bw[0];
    }

    stage_h16<8>(Ws, W2h + 128, 192, 128, 128, LDHB);
    stage_h(Xs, bond + eb * 64, 64, 0, 128, 128, 16, LDHB);
    __syncthreads();

    float c[4][4][4];
#pragma unroll
    for (int mt = 0; mt < 4; mt++)
#pragma unroll
        for (int ntl = 0; ntl < 4; ntl++)
#pragma unroll
            for (int r = 0; r < 4; r++) c[mt][ntl][r] = 0.f;

    mma_loop_h<4, LDHB>(Xs, Ws, wm, wn, g, tg, c);

#pragma unroll
    for (int mt = 0; mt < 4; mt++) {
        int r0 = wm * 64 + mt * 16 + g;
        const __half2* p0r = (const __half2*)(P + (size_t)ssrc[r0] * 128);
        const __half2* p1r = (const __half2*)(P + (size_t)ssrc[r0 + 8] * 128);
        float s0 = 0.f, s1 = 0.f;
#pragma unroll
        for (int ntl = 0; ntl < 4; ntl++) {
            int col = wn * 32 + ntl * 8 + tg * 2;
            float w0 = __ldg(Ww + 128 + col), w1 = __ldg(Ww + 128 + col + 1);
            float2 pa = __half22float2(p0r[col >> 1]);
            float2 pb = __half22float2(p1r[col >> 1]);
            s0 += lrelu_f(c[mt][ntl][0] + pa.x) * w0 + lrelu_f(c[mt][ntl][1] + pa.y) * w1;
            s1 += lrelu_f(c[mt][ntl][2] + pb.x) * w0 + lrelu_f(c[mt][ntl][3] + pb.y) * w1;
        }
        s0 += __shfl_xor_sync(0xffffffffu, s0, 1);
        s0 += __shfl_xor_sync(0xffffffffu, s0, 2);
        s1 += __shfl_xor_sync(0xffffffffu, s1, 1);
        s1 += __shfl_xor_sync(0xffffffffu, s1, 2);
        if (tg == 0) {
            slog[wn * 128 + r0]     = s0;
            slog[wn * 128 + r0 + 8] = s1;
        }
    }
    __syncthreads();

    if (tid < 16) {
        float base = sndot[tid];
        float l[8];
        float m = -1e30f;
#pragma unroll
        for (int e = 0; e < 8; e++) {
            int i = tid * 8 + e;
            float v = slog[i] + slog[128 + i] + slog[256 + i] + slog[384 + i];
            v = lrelu_f(v + base);
            l[e] = v;
            m = fmaxf(m, v);
        }
        float ssum = 0.f;
#pragma unroll
        for (int e = 0; e < 8; e++) { l[e] = expf(l[e] - m); ssum += l[e]; }
        float inv = 1.f / ssum;
        float* so = scr + eb + tid * 8;
#pragma unroll
        for (int e = 0; e < 8; e++) so[e] = l[e] * inv;
    }
}

// ---------------------------------------------------------------------------
// Context gather: ctx[n] = elu( sum_e scr[n,e] * nt[src[n,e]] )  (fp16 nt/ctx)
// ---------------------------------------------------------------------------
__global__ __launch_bounds__(256)
void ctx_gather(const int* __restrict__ src, const float* __restrict__ scr,
                const __half* __restrict__ nt, __half* __restrict__ ctx) {
    const int tid = threadIdx.x;
    const int lane = tid & 31;
    const int gn = blockIdx.x * 16 + (tid >> 4);
    const int l = tid & 15;

    int   se8 = 0;
    float sc8 = 0.f;
    if ((lane & 15) < 8) {
        se8 = src[(size_t)gn * 8 + (lane & 15)];
        sc8 = scr[(size_t)gn * 8 + (lane & 15)];
    }

    float a[8];
#pragma unroll
    for (int q = 0; q < 8; q++) a[q] = 0.f;

#pragma unroll
    for (int e = 0; e < 8; e++) {
        int   sl = (lane & 16) | e;
        int   sidx = __shfl_sync(0xffffffffu, se8, sl, 32);
        float sc   = __shfl_sync(0xffffffffu, sc8, sl, 32);
        uint4 v = *(const uint4*)(nt + (size_t)sidx * 128 + l * 8);
        float2 f0 = u2f2(v.x), f1 = u2f2(v.y), f2 = u2f2(v.z), f3 = u2f2(v.w);
        a[0] += sc * f0.x; a[1] += sc * f0.y; a[2] += sc * f1.x; a[3] += sc * f1.y;
        a[4] += sc * f2.x; a[5] += sc * f2.y; a[6] += sc * f3.x; a[7] += sc * f3.y;
    }
#pragma unroll
    for (int q = 0; q < 8; q++) a[q] = a[q] > 0.f ? a[q] : (expf(a[q]) - 1.f);
    uint4 o;
    o.x = h2u(__floats2half2_rn(a[0], a[1]));
    o.y = h2u(__floats2half2_rn(a[2], a[3]));
    o.z = h2u(__floats2half2_rn(a[4], a[5]));
    o.w = h2u(__floats2half2_rn(a[6], a[7]));
    *(uint4*)(ctx + (size_t)gn * 128 + l * 8) = o;
}

// ---------------------------------------------------------------------------
// GRU elementwise combine (gi/gh fp16, h1/out fp32). 8 cols per thread.
// ---------------------------------------------------------------------------
__global__ __launch_bounds__(256)
void gru_combine(const __half* __restrict__ gi, const __half* __restrict__ gh,
                 const float* __restrict__ h1, float* __restrict__ out) {
    int i = blockIdx.x * blockDim.x + threadIdx.x;
    if (i >= NN * 16) return;
    int n = i >> 4, c0 = (i & 15) * 8;
    const __half* gin = gi + (size_t)n * 384;
    const __half* ghn = gh + (size_t)n * 384;

    uint4 ir8 = *(const uint4*)(gin + c0);
    uint4 iz8 = *(const uint4*)(gin + 128 + c0);
    uint4 in8 = *(const uint4*)(gin + 256 + c0);
    uint4 hr8 = *(const uint4*)(ghn + c0);
    uint4 hz8 = *(const uint4*)(ghn + 128 + c0);
    uint4 hn8 = *(const uint4*)(ghn + 256 + c0);

    float irv[8], izv[8], inv_[8], hrv[8], hzv[8], hnv[8];
    {
        float2 t;
        t = u2f2(ir8.x); irv[0]=t.x; irv[1]=t.y;  t = u2f2(ir8.y); irv[2]=t.x; irv[3]=t.y;
        t = u2f2(ir8.z); irv[4]=t.x; irv[5]=t.y;  t = u2f2(ir8.w); irv[6]=t.x; irv[7]=t.y;
        t = u2f2(iz8.x); izv[0]=t.x; izv[1]=t.y;  t = u2f2(iz8.y); izv[2]=t.x; izv[3]=t.y;
        t = u2f2(iz8.z); izv[4]=t.x; izv[5]=t.y;  t = u2f2(iz8.w); izv[6]=t.x; izv[7]=t.y;
        t = u2f2(in8.x); inv_[0]=t.x; inv_[1]=t.y; t = u2f2(in8.y); inv_[2]=t.x; inv_[3]=t.y;
        t = u2f2(in8.z); inv_[4]=t.x; inv_[5]=t.y; t = u2f2(in8.w); inv_[6]=t.x; inv_[7]=t.y;
        t = u2f2(hr8.x); hrv[0]=t.x; hrv[1]=t.y;  t = u2f2(hr8.y); hrv[2]=t.x; hrv[3]=t.y;
        t = u2f2(hr8.z); hrv[4]=t.x; hrv[5]=t.y;  t = u2f2(hr8.w); hrv[6]=t.x; hrv[7]=t.y;
        t = u2f2(hz8.x); hzv[0]=t.x; hzv[1]=t.y;  t = u2f2(hz8.y); hzv[2]=t.x; hzv[3]=t.y;
        t = u2f2(hz8.z); hzv[4]=t.x; hzv[5]=t.y;  t = u2f2(hz8.w); hzv[6]=t.x; hzv[7]=t.y;
        t = u2f2(hn8.x); hnv[0]=t.x; hnv[1]=t.y;  t = u2f2(hn8.y); hnv[2]=t.x; hnv[3]=t.y;
        t = u2f2(hn8.z); hnv[4]=t.x; hnv[5]=t.y;  t = u2f2(hn8.w); hnv[6]=t.x; hnv[7]=t.y;
    }

    const float* h1r = h1 + (size_t)n * 128 + c0;
    float* orow = out + (size_t)n * 128 + c0;
    float4 h0 = *(const float4*)(h1r);
    float4 h1v = *(const float4*)(h1r + 4);
    float hv[8] = {h0.x, h0.y, h0.z, h0.w, h1v.x, h1v.y, h1v.z, h1v.w};
    float ov[8];
#pragma unroll
    for (int q = 0; q < 8; q++) {
        float r = 1.f / (1.f + expf(-(irv[q] + hrv[q])));
        float z = 1.f / (1.f + expf(-(izv[q] + hzv[q])));
        float nv = tanhf(inv_[q] + r * hnv[q]);
        ov[q] = (1.f - z) * nv + z * hv[q];
    }
    *(float4*)(orow)     = make_float4(ov[0], ov[1], ov[2], ov[3]);
    *(float4*)(orow + 4) = make_float4(ov[4], ov[5], ov[6], ov[7]);
}

// ---------------------------------------------------------------------------
extern "C" void kernel_launch(void* const* d_in, const int* in_sizes, int n_in,
                              void* d_out, int out_size) {
    const float* atom = (const float*)d_in[0];
    const float* bond = (const float*)d_in[1];
    const int*   src  = (const int*)d_in[2];
    // d_in[3] = dst (structurally e/8; unused)
    const float* W1   = (const float*)d_in[4];
    const float* b1   = (const float*)d_in[5];
    const float* W2   = (const float*)d_in[6];
    const float* b2   = (const float*)d_in[7];
    const float* Wa   = (const float*)d_in[8];
    const float* ba   = (const float*)d_in[9];
    const float* Ww   = (const float*)d_in[10];
    const float* bw   = (const float*)d_in[11];
    const float* W_ih = (const float*)d_in[12];
    const float* b_ih = (const float*)d_in[13];
    const float* W_hh = (const float*)d_in[14];
    const float* b_hh = (const float*)d_in[15];

    float* out = (float*)d_out;

    __half *nt, *ctx, *P, *gi, *gh, *h1h, *W1h, *Wah, *W2h, *Wihh, *Whhh;
    float *scr, *h1fb;
    cudaGetSymbolAddress((void**)&nt,   g_nt);
    cudaGetSymbolAddress((void**)&ctx,  g_ctx);
    cudaGetSymbolAddress((void**)&P,    g_P);
    cudaGetSymbolAddress((void**)&gi,   g_gi);
    cudaGetSymbolAddress((void**)&gh,   g_gh);
    cudaGetSymbolAddress((void**)&h1h,  g_h1h);
    cudaGetSymbolAddress((void**)&scr,  g_scr);
    cudaGetSymbolAddress((void**)&h1fb, g_h1);
    cudaGetSymbolAddress((void**)&W1h,  g_W1h);
    cudaGetSymbolAddress((void**)&Wah,  g_Wah);
    cudaGetSymbolAddress((void**)&W2h,  g_W2h);
    cudaGetSymbolAddress((void**)&Wihh, g_Wihh);
    cudaGetSymbolAddress((void**)&Whhh, g_Whhh);

    float* h1 = (out_size >= 2 * NN * 128) ? (out + (size_t)NN * 128) : h1fb;

    const int GSM = 2 * 128 * LDH * 4;                                  // 67584
    const int ESM = 2 * 128 * LDHB * 4 + (4 * 128 + 16) * 4 + 128 * 4;  // ~37.5 KB

    cudaFuncSetAttribute((tc_gemm<1, false, false, true, 1>), cudaFuncAttributeMaxDynamicSharedMemorySize, GSM);
    cudaFuncSetAttribute((tc_gemm<0, false, true, false, 1>), cudaFuncAttributeMaxDynamicSharedMemorySize, GSM);
    cudaFuncSetAttribute((tc_gemm<0, true, true, false, 1>),  cudaFuncAttributeMaxDynamicSharedMemorySize, GSM);
    cudaFuncSetAttribute((tc_gemm<0, true, true, false, 3>),  cudaFuncAttributeMaxDynamicSharedMemorySize, GSM);
    cudaFuncSetAttribute(edge_kernel, cudaFuncAttributeMaxDynamicSharedMemorySize, ESM);

    // persistent side streams + fork/join events
    static cudaStream_t s2 = nullptr, s3 = nullptr;
    static cudaEvent_t ev0 = nullptr, evP = nullptr, evH = nullptr;
    static cudaEvent_t evNT = nullptr, evGH = nullptr;
    if (!s2) {
        cudaStreamCreateWithFlags(&s2, cudaStreamNonBlocking);
        cudaStreamCreateWithFlags(&s3, cudaStreamNonBlocking);
        cudaEventCreateWithFlags(&ev0, cudaEventDisableTiming);
        cudaEventCreateWithFlags(&evP, cudaEventDisableTiming);
        cudaEventCreateWithFlags(&evH, cudaEventDisableTiming);
        cudaEventCreateWithFlags(&evNT, cudaEventDisableTiming);
        cudaEventCreateWithFlags(&evGH, cudaEventDisableTiming);
    }

    const int MB = (NN + 127) / 128;  // 782

    // 0) weight pre-convert (tiny) on main, then fork
    wconvert<<<192, 256>>>(W1, Wa, W2, W_ih, W_hh);
    cudaEventRecord(ev0, 0);
    cudaStreamWaitEvent(s2, ev0, 0);
    cudaStreamWaitEvent(s3, ev0, 0);

    // main: h1 = lrelu(atom @ W1^T + b1) -> fp32 (output) + fp16 shadow
    tc_gemm<1, false, false, true, 1><<<MB, 256, GSM>>>(atom, W1h, b1, h1, h1h, NN, 128);
    cudaEventRecord(evH, 0);

    // s2: P = atom @ W2a^T + b2 -> fp16   (independent of h1)
    tc_gemm<0, false, true, false, 1><<<MB, 256, GSM, s2>>>(atom, W2h, b2, P, nullptr, NN, 192);
    cudaEventRecord(evP, s2);

    // s3: nt then gh (both need only h1h; overlap the edge kernel)
    cudaStreamWaitEvent(s3, evH, 0);
    tc_gemm<0, true, true, false, 1><<<MB, 256, GSM, s3>>>(h1h, Wah, ba, nt, nullptr, NN, 128);
    cudaEventRecord(evNT, s3);
    tc_gemm<0, true, true, false, 3><<<MB, 256, GSM, s3>>>(h1h, Whhh, b_hh, gh, nullptr, NN, 128);
    cudaEventRecord(evGH, s3);

    // main: edge logits + softmax -> scores (needs h1 + P only)
    cudaStreamWaitEvent(0, evP, 0);
    edge_kernel<<<NN / 16, 256, ESM>>>(bond, src, h1, P, W2h, Ww, bw, scr);

    // main: ctx = elu(weighted gather of nt)
    cudaStreamWaitEvent(0, evNT, 0);
    ctx_gather<<<NN / 16, 256>>>(src, scr, nt, ctx);

    // main: gi = ctx @ W_ih^T + b_ih -> fp16 (A resident across 3 n-tiles)
    tc_gemm<0, true, true, false, 3><<<MB, 256, GSM>>>(ctx, Wihh, b_ih, gi, nullptr, NN, 128);

    // main: combine (needs gi + gh)
    cudaStreamWaitEvent(0, evGH, 0);
    gru_combine<<<(NN * 16 + 255) / 256, 256>>>(gi, gh, h1, out);
}